// round 5
// baseline (speedup 1.0000x reference)
#include <cuda_runtime.h>

#define PH 7
#define PW 7
#define G  7
#define D  8
#define C  (D * G * G)      // 392
#define H  96
#define W  96
#define R  512
#define SCALEF 0.0625f
#define OUT_PER_ROI (D * PH * PW)   // 392
#define MAXEXT 6        // max bin extent per axis (ceil(480*0.0625/7)+1)
#define GRP 8           // lanes per output bin
#define GROUPS_PER_BLK 56
#define THREADS (GROUPS_PER_BLK * GRP)   // 448
#define BLKS_PER_ROI (OUT_PER_ROI / GROUPS_PER_BLK)  // 7

__global__ __launch_bounds__(THREADS, 4) void psroi_kernel(
    const float* __restrict__ feat,   // [B, C, H, W]
    const float* __restrict__ rois,   // [R, 5]
    float* __restrict__ out)          // [R, D, PH, PW]
{
    const int r = blockIdx.x;
    const int t = threadIdx.x;

    __shared__ int   s_b;
    __shared__ int   s_hs[PH], s_he[PH], s_ws[PW], s_we[PW];
    __shared__ float s_invh[PH], s_invw[PW];

    if (t == 0) {
        s_b = (int)rois[r * 5 + 0];
    }
    // vertical bins (p -> rows h), threads 0..6
    if (t < PH) {
        const int p = t;
        float y1 = __fmul_rn(rintf(rois[r * 5 + 2]), SCALEF);
        float y2 = __fmul_rn(rintf(__fadd_rn(rois[r * 5 + 4], 1.0f)), SCALEF);
        float rh = fmaxf(__fsub_rn(y2, y1), 0.1f);
        float bs = __fdiv_rn(rh, (float)PH);
        float sv = fminf(fmaxf(floorf(__fadd_rn(__fmul_rn((float)p,       bs), y1)), 0.0f), (float)H);
        float ev = fminf(fmaxf(ceilf (__fadd_rn(__fmul_rn((float)(p + 1), bs), y1)), 0.0f), (float)H);
        s_hs[p] = (int)sv;
        s_he[p] = (int)ev;
        float n = fmaxf(__fsub_rn(ev, sv), 0.0f);
        s_invh[p] = 1.0f / fmaxf(n, 1.0f);
    }
    // horizontal bins (q -> cols w), threads 32..38 (separate warp)
    if (t >= 32 && t < 32 + PW) {
        const int q = t - 32;
        float x1 = __fmul_rn(rintf(rois[r * 5 + 1]), SCALEF);
        float x2 = __fmul_rn(rintf(__fadd_rn(rois[r * 5 + 3], 1.0f)), SCALEF);
        float rw = fmaxf(__fsub_rn(x2, x1), 0.1f);
        float bs = __fdiv_rn(rw, (float)PW);
        float sv = fminf(fmaxf(floorf(__fadd_rn(__fmul_rn((float)q,       bs), x1)), 0.0f), (float)W);
        float ev = fminf(fmaxf(ceilf (__fadd_rn(__fmul_rn((float)(q + 1), bs), x1)), 0.0f), (float)W);
        s_ws[q] = (int)sv;
        s_we[q] = (int)ev;
        float n = fmaxf(__fsub_rn(ev, sv), 0.0f);
        s_invw[q] = 1.0f / fmaxf(n, 1.0f);
    }
    __syncthreads();

    // 8 lanes per output bin; lanes map along w (contiguous -> coalesced).
    const int g = t >> 3;              // group 0..55
    const int l = t & 7;               // lane-in-group, covers w offset
    const int o = blockIdx.y * GROUPS_PER_BLK + g;   // output/channel 0..391

    const int q = o % PW;
    const int p = (o / PW) % PH;

    const int hs = s_hs[p], eh = s_he[p] - hs;   // 0..6 rows
    const int ws = s_ws[q], ew = s_we[q] - ws;   // 0..6 cols

    const float* base = feat + ((size_t)s_b * C + o) * (H * W) + hs * W + ws;

    // up to 6 rows, one coalesced group-load per row, all independent
    float v = 0.0f;
    const bool lane_ok = (l < ew);
    #pragma unroll
    for (int k = 0; k < MAXEXT; ++k) {
        float x = (lane_ok && k < eh) ? __ldg(base + k * W + l) : 0.0f;
        v += x;
    }

    // reduce across the 8-lane group (groups are lane-aligned within warp)
    v += __shfl_xor_sync(0xffffffffu, v, 4);
    v += __shfl_xor_sync(0xffffffffu, v, 2);
    v += __shfl_xor_sync(0xffffffffu, v, 1);

    if (l == 0) {
        out[(size_t)r * OUT_PER_ROI + o] = v * s_invh[p] * s_invw[q];
    }
}

extern "C" void kernel_launch(void* const* d_in, const int* in_sizes, int n_in,
                              void* d_out, int out_size)
{
    const float* feat = (const float*)d_in[0];
    const float* rois = (const float*)d_in[1];
    float* out        = (float*)d_out;

    dim3 grid(R, BLKS_PER_ROI);
    psroi_kernel<<<grid, THREADS>>>(feat, rois, out);
}

// round 6
// speedup vs baseline: 1.3353x; 1.3353x over previous
#include <cuda_runtime.h>

#define PH 7
#define PW 7
#define G  7
#define D  8
#define C  (D * G * G)      // 392
#define H  96
#define W  96
#define R  512
#define SCALEF 0.0625f
#define OUT_PER_ROI (D * PH * PW)   // 392
#define MAXEXT 6        // max bin extent per axis
#define GRP 8           // lanes per roi-bin group
#define TPB 256
#define ROIS_PER_BLK 256
#define NGROUP (TPB / GRP)              // 32 groups per block
#define NPASS (ROIS_PER_BLK / NGROUP)   // 8 passes

__global__ __launch_bounds__(TPB, 6) void psroi_kernel(
    const float* __restrict__ feat,   // [B, C, H, W]
    const float* __restrict__ rois,   // [R, 5]
    float* __restrict__ out)          // [R, D, PH, PW]
{
    const int c  = blockIdx.x;             // channel 0..391 (== d*49 + p*7 + q)
    const int r0 = blockIdx.y * ROIS_PER_BLK;
    const int t  = threadIdx.x;

    const int q = c % PW;
    const int p = (c / PW) % PH;

    __shared__ int   s_geo[ROIS_PER_BLK];   // hs | he<<8 | ws<<16 | we<<24
    __shared__ int   s_bb [ROIS_PER_BLK];   // batch index
    __shared__ float s_invh[ROIS_PER_BLK];
    __shared__ float s_invw[ROIS_PER_BLK];

    // ---- phase 1: per-roi bin geometry for THIS channel's (p,q), one roi/thread
    {
        const int r = r0 + t;
        const float* rp = rois + (size_t)r * 5;
        const float bidx = rp[0];
        float x1 = __fmul_rn(rintf(rp[1]), SCALEF);
        float y1 = __fmul_rn(rintf(rp[2]), SCALEF);
        float x2 = __fmul_rn(rintf(__fadd_rn(rp[3], 1.0f)), SCALEF);
        float y2 = __fmul_rn(rintf(__fadd_rn(rp[4], 1.0f)), SCALEF);
        float rw = fmaxf(__fsub_rn(x2, x1), 0.1f);
        float rh = fmaxf(__fsub_rn(y2, y1), 0.1f);
        float bsw = __fdiv_rn(rw, (float)PW);
        float bsh = __fdiv_rn(rh, (float)PH);

        float hsf = fminf(fmaxf(floorf(__fadd_rn(__fmul_rn((float)p,       bsh), y1)), 0.0f), (float)H);
        float hef = fminf(fmaxf(ceilf (__fadd_rn(__fmul_rn((float)(p + 1), bsh), y1)), 0.0f), (float)H);
        float wsf = fminf(fmaxf(floorf(__fadd_rn(__fmul_rn((float)q,       bsw), x1)), 0.0f), (float)W);
        float wef = fminf(fmaxf(ceilf (__fadd_rn(__fmul_rn((float)(q + 1), bsw), x1)), 0.0f), (float)W);

        s_geo[t] = ((int)hsf) | (((int)hef) << 8) | (((int)wsf) << 16) | (((int)wef) << 24);
        s_bb [t] = (int)bidx;
        float nh = fmaxf(__fsub_rn(hef, hsf), 0.0f);
        float nw = fmaxf(__fsub_rn(wef, wsf), 0.0f);
        s_invh[t] = 1.0f / fmaxf(nh, 1.0f);
        s_invw[t] = 1.0f / fmaxf(nw, 1.0f);
    }
    __syncthreads();

    // ---- phase 2: 8-lane groups, one roi-bin per group per pass, coalesced rows
    const int g = t >> 3;      // group 0..31
    const int l = t & 7;       // lane-in-group = w offset

    #pragma unroll
    for (int pass = 0; pass < NPASS; ++pass) {
        const int rl  = pass * NGROUP + g;
        const int geo = s_geo[rl];
        const int hs  =  geo        & 0xff;
        const int he  = (geo >> 8)  & 0xff;
        const int ws  = (geo >> 16) & 0xff;
        const int we  = (geo >> 24) & 0xff;
        const int eh  = he - hs;
        const int ew  = we - ws;

        const float* base = feat + ((size_t)(s_bb[rl] * C + c)) * (H * W) + hs * W + ws;

        float v = 0.0f;
        const bool lok = (l < ew);
        #pragma unroll
        for (int k = 0; k < MAXEXT; ++k) {
            v += (lok && k < eh) ? __ldg(base + k * W + l) : 0.0f;
        }

        v += __shfl_xor_sync(0xffffffffu, v, 4);
        v += __shfl_xor_sync(0xffffffffu, v, 2);
        v += __shfl_xor_sync(0xffffffffu, v, 1);

        if (l == 0) {
            out[(size_t)(r0 + rl) * OUT_PER_ROI + c] = v * s_invh[rl] * s_invw[rl];
        }
    }
}

extern "C" void kernel_launch(void* const* d_in, const int* in_sizes, int n_in,
                              void* d_out, int out_size)
{
    const float* feat = (const float*)d_in[0];
    const float* rois = (const float*)d_in[1];
    float* out        = (float*)d_out;

    dim3 grid(C, R / ROIS_PER_BLK);   // (392, 2)
    psroi_kernel<<<grid, TPB>>>(feat, rois, out);
}